// round 1
// baseline (speedup 1.0000x reference)
#include <cuda_runtime.h>
#include <cstdint>

#define NN   65536
#define EE   262144
#define EDIMC 300
#define HD   256
#define KC   556   // EDIM + HDIM
#define N3H  768   // 3*HDIM

// ---- scratch (device globals; no allocation allowed) ----
__device__ float g_h_tilde[(size_t)NN * HD];   //  67 MB
__device__ float g_fx     [(size_t)NN * HD];   //  67 MB
__device__ float g_hU     [(size_t)EE * HD];   // 268 MB
__device__ float g_fc     [(size_t)NN * HD];   //  67 MB
__device__ float g_big    [(size_t)NN * N3H];  // 201 MB
__device__ int   g_rowstart[NN + 1];

// ---------------------------------------------------------------------------
// CSR row starts: segment_ids is sorted; row_start[j] = lower_bound(seg, j)
// ---------------------------------------------------------------------------
__global__ void k_rowstart(const int* __restrict__ seg) {
    int j = blockIdx.x * blockDim.x + threadIdx.x;
    if (j > NN) return;
    int lo = 0, hi = EE;
    while (lo < hi) {
        int mid = (lo + hi) >> 1;
        if (seg[mid] < j) lo = mid + 1; else hi = mid;
    }
    g_rowstart[j] = lo;
}

// ---------------------------------------------------------------------------
// h_tilde[j] = sum over children k of prev_h[k]   (one block per node)
// ---------------------------------------------------------------------------
__global__ void k_segsum(const float* __restrict__ prev_h) {
    int j = blockIdx.x, d = threadIdx.x;
    int s = g_rowstart[j], e = g_rowstart[j + 1];
    float acc = 0.f;
    for (int k = s; k < e; k++)
        acc += prev_h[(size_t)k * HD + d];
    g_h_tilde[(size_t)j * HD + d] = acc;
}

// ---------------------------------------------------------------------------
// fc_term[j] = sum over children k of sigmoid(fx[j] + hU[k] + b_f) * prev_c[k]
// ---------------------------------------------------------------------------
__global__ void k_edge(const float* __restrict__ prev_c, const float* __restrict__ b_f) {
    int j = blockIdx.x, d = threadIdx.x;
    int s = g_rowstart[j], e = g_rowstart[j + 1];
    float base = g_fx[(size_t)j * HD + d] + b_f[d];
    float acc = 0.f;
    for (int k = s; k < e; k++) {
        float z = base + g_hU[(size_t)k * HD + d];
        float f = 1.f / (1.f + __expf(-z));
        acc += f * prev_c[(size_t)k * HD + d];
    }
    g_fc[(size_t)j * HD + d] = acc;
}

// ---------------------------------------------------------------------------
// final: c = sigmoid(z_i)*tanh(z_u) + fc;  h = sigmoid(z_o)*tanh(c)
// output layout: out[0 : N*H] = c, out[N*H : 2*N*H] = h
// ---------------------------------------------------------------------------
__device__ __forceinline__ float sigm_f(float x) { return 1.f / (1.f + __expf(-x)); }
__device__ __forceinline__ float tanh_f(float x) { return 1.f - 2.f / (__expf(2.f * x) + 1.f); }

__global__ void k_final(float* __restrict__ out) {
    int j = blockIdx.x, d = threadIdx.x;
    size_t b = (size_t)j * N3H;
    float zi = g_big[b + d];
    float zo = g_big[b + HD + d];
    float zu = g_big[b + 2 * HD + d];
    float c = sigm_f(zi) * tanh_f(zu) + g_fc[(size_t)j * HD + d];
    float h = sigm_f(zo) * tanh_f(c);
    out[(size_t)j * HD + d] = c;
    out[(size_t)NN * HD + (size_t)j * HD + d] = h;
}

// ---------------------------------------------------------------------------
// TF32 mma.sync GEMM: C[M,ldc tile] = A[M,K] @ B[K,ldb] (+bias)
// MODE 0: plain A, row stride = K.
// MODE 1: A row = concat(x[row,0:300], h_tilde[row,0:256]), K = 556.
// CTA tile 128x128x16, 8 warps (4x2), warp tile 32x64, double-buffered smem.
// ---------------------------------------------------------------------------
__device__ __forceinline__ uint32_t f2tf32(float f) {
    uint32_t u;
    asm("cvt.rna.tf32.f32 %0, %1;" : "=r"(u) : "f"(f));
    return u;
}

#define MMA_TF32(d, a, b)                                                      \
    asm volatile("mma.sync.aligned.m16n8k8.row.col.f32.tf32.tf32.f32 "         \
                 "{%0,%1,%2,%3}, {%4,%5,%6,%7}, {%8,%9}, {%0,%1,%2,%3};"       \
                 : "+f"(d[0]), "+f"(d[1]), "+f"(d[2]), "+f"(d[3])              \
                 : "r"(a[0]), "r"(a[1]), "r"(a[2]), "r"(a[3]),                 \
                   "r"(b[0]), "r"(b[1]))

#define LDA_S 20   // padded A smem stride (conflict-free, 16B aligned)
#define LDB_S 132  // padded B smem stride (conflict-free, 16B aligned)

template <int MODE>
__global__ __launch_bounds__(256)
void k_gemm(const float* __restrict__ A, const float* __restrict__ A2,
            const float* __restrict__ B, float* __restrict__ C,
            const float* __restrict__ bias, int M, int K, int ldb, int ldc) {
    constexpr int BM = 128, BN = 128, BK = 16;
    __shared__ float As[2][BM * LDA_S];
    __shared__ float Bs[2][BK * LDB_S];

    const int tid = threadIdx.x;
    const int lane = tid & 31, wid = tid >> 5;
    const int warp_m = wid >> 1;          // 0..3  (32 rows each)
    const int warp_n = wid & 1;           // 0..1  (64 cols each)
    const int qid = lane >> 2, t4 = lane & 3;
    const int bm0 = blockIdx.x * BM, bn0 = blockIdx.y * BN;

    float acc[2][8][4];
#pragma unroll
    for (int mi = 0; mi < 2; mi++)
#pragma unroll
        for (int ni = 0; ni < 8; ni++)
#pragma unroll
            for (int r = 0; r < 4; r++) acc[mi][ni][r] = 0.f;

    const int nk = (K + BK - 1) / BK;
    float4 aR[2], bR[2];

    auto loadG = [&](int kt) {
        int k0 = kt * BK;
#pragma unroll
        for (int i = 0; i < 2; i++) {
            int lin = tid + i * 256;
            int row = lin >> 2, kq = lin & 3;
            int gr = bm0 + row, gk = k0 + kq * 4;
            float4 v = make_float4(0.f, 0.f, 0.f, 0.f);
            if (MODE == 0) {
                if (gk < K) v = *(const float4*)(A + (size_t)gr * K + gk);
            } else {
                if (gk < EDIMC)    v = *(const float4*)(A  + (size_t)gr * EDIMC + gk);
                else if (gk < KC)  v = *(const float4*)(A2 + (size_t)gr * HD + (gk - EDIMC));
            }
            aR[i] = v;
        }
#pragma unroll
        for (int i = 0; i < 2; i++) {
            int lin = tid + i * 256;
            int row = lin >> 5, cq = lin & 31;
            int gk = k0 + row, gc = bn0 + cq * 4;
            float4 v = make_float4(0.f, 0.f, 0.f, 0.f);
            if (gk < K) v = *(const float4*)(B + (size_t)gk * ldb + gc);
            bR[i] = v;
        }
    };

    auto storeS = [&](int buf) {
#pragma unroll
        for (int i = 0; i < 2; i++) {
            int lin = tid + i * 256;
            int row = lin >> 2, kq = lin & 3;
            float* p = &As[buf][row * LDA_S + kq * 4];
            p[0] = __uint_as_float(f2tf32(aR[i].x));
            p[1] = __uint_as_float(f2tf32(aR[i].y));
            p[2] = __uint_as_float(f2tf32(aR[i].z));
            p[3] = __uint_as_float(f2tf32(aR[i].w));
        }
#pragma unroll
        for (int i = 0; i < 2; i++) {
            int lin = tid + i * 256;
            int row = lin >> 5, cq = lin & 31;
            float* p = &Bs[buf][row * LDB_S + cq * 4];
            p[0] = __uint_as_float(f2tf32(bR[i].x));
            p[1] = __uint_as_float(f2tf32(bR[i].y));
            p[2] = __uint_as_float(f2tf32(bR[i].z));
            p[3] = __uint_as_float(f2tf32(bR[i].w));
        }
    };

    auto compute = [&](int buf) {
#pragma unroll
        for (int kk = 0; kk < BK; kk += 8) {
            uint32_t af[2][4];
#pragma unroll
            for (int mi = 0; mi < 2; mi++) {
                int r0 = warp_m * 32 + mi * 16 + qid;
                const float* Ab = As[buf];
                af[mi][0] = __float_as_uint(Ab[r0 * LDA_S + kk + t4]);
                af[mi][1] = __float_as_uint(Ab[(r0 + 8) * LDA_S + kk + t4]);
                af[mi][2] = __float_as_uint(Ab[r0 * LDA_S + kk + t4 + 4]);
                af[mi][3] = __float_as_uint(Ab[(r0 + 8) * LDA_S + kk + t4 + 4]);
            }
            uint32_t bf[8][2];
#pragma unroll
            for (int ni = 0; ni < 8; ni++) {
                int cn = warp_n * 64 + ni * 8 + qid;
                const float* Bb = Bs[buf];
                bf[ni][0] = __float_as_uint(Bb[(kk + t4) * LDB_S + cn]);
                bf[ni][1] = __float_as_uint(Bb[(kk + t4 + 4) * LDB_S + cn]);
            }
#pragma unroll
            for (int mi = 0; mi < 2; mi++)
#pragma unroll
                for (int ni = 0; ni < 8; ni++)
                    MMA_TF32(acc[mi][ni], af[mi], bf[ni]);
        }
    };

    loadG(0);
    storeS(0);
    __syncthreads();
    int buf = 0;
    for (int kt = 0; kt < nk; kt++) {
        bool hasNext = (kt + 1 < nk);
        if (hasNext) loadG(kt + 1);
        compute(buf);
        if (hasNext) {
            storeS(buf ^ 1);
            __syncthreads();
            buf ^= 1;
        }
    }

    // epilogue
#pragma unroll
    for (int mi = 0; mi < 2; mi++)
#pragma unroll
        for (int ni = 0; ni < 8; ni++) {
            int row = bm0 + warp_m * 32 + mi * 16 + qid;
            int col = bn0 + warp_n * 64 + ni * 8 + t4 * 2;
            float b0 = 0.f, b1 = 0.f;
            if (bias) { b0 = bias[col]; b1 = bias[col + 1]; }
            float* p0 = &C[(size_t)row * ldc + col];
            p0[0] = acc[mi][ni][0] + b0;
            p0[1] = acc[mi][ni][1] + b1;
            float* p1 = &C[(size_t)(row + 8) * ldc + col];
            p1[0] = acc[mi][ni][2] + b0;
            p1[1] = acc[mi][ni][3] + b1;
        }
}

// ---------------------------------------------------------------------------
extern "C" void kernel_launch(void* const* d_in, const int* in_sizes, int n_in,
                              void* d_out, int out_size) {
    const float* x      = (const float*)d_in[0];
    const float* prev_c = (const float*)d_in[1];
    const float* prev_h = (const float*)d_in[2];
    const float* Wc     = (const float*)d_in[3];
    const float* bc     = (const float*)d_in[4];
    const float* Wf     = (const float*)d_in[5];
    const float* Uf     = (const float*)d_in[6];
    const float* bf     = (const float*)d_in[7];
    const int*   seg    = (const int*)d_in[8];
    float* out = (float*)d_out;

    float *p_ht, *p_fx, *p_hU, *p_fc, *p_big;
    cudaGetSymbolAddress((void**)&p_ht,  g_h_tilde);
    cudaGetSymbolAddress((void**)&p_fx,  g_fx);
    cudaGetSymbolAddress((void**)&p_hU,  g_hU);
    cudaGetSymbolAddress((void**)&p_fc,  g_fc);
    cudaGetSymbolAddress((void**)&p_big, g_big);

    k_rowstart<<<(NN + 1 + 255) / 256, 256>>>(seg);
    k_segsum<<<NN, 256>>>(prev_h);

    // fx = x @ W_f                       [65536,300] @ [300,256]
    dim3 g2(NN / 128, HD / 128);
    k_gemm<0><<<g2, 256>>>(x, nullptr, Wf, p_fx, nullptr, NN, EDIMC, HD, HD);

    // hU = prev_h @ U_f                  [262144,256] @ [256,256]
    dim3 g3(EE / 128, HD / 128);
    k_gemm<0><<<g3, 256>>>(prev_h, nullptr, Uf, p_hU, nullptr, EE, HD, HD, HD);

    // fc_term
    k_edge<<<NN, 256>>>(prev_c, bf);

    // big = [x | h_tilde] @ W_combined + b_combined   [65536,556] @ [556,768]
    dim3 g1(NN / 128, N3H / 128);
    k_gemm<1><<<g1, 256>>>(x, p_ht, Wc, p_big, bc, NN, KC, N3H, N3H);

    k_final<<<NN, 256>>>(out);
}